// round 8
// baseline (speedup 1.0000x reference)
#include <cuda_runtime.h>

#define HH 512
#define WW 512
#define NPIX (HH*WW)
#define BSZ 64
#define THREADS 256
#define STRIPS 16                 // blocks per batch
#define STRIP_PIX (NPIX / STRIPS) // 16384 pixels per strip
#define ITER_PIX (THREADS * 4)    // 1024 pixels per iteration
#define ITERS (STRIP_PIX / ITER_PIX) // 16

__global__ __launch_bounds__(THREADS, 7) void uv_transform_kernel(
    const float* __restrict__ depth,
    const float* __restrict__ R0g,
    const float* __restrict__ t0g,
    const float* __restrict__ R1g,
    const float* __restrict__ t1g,
    const float* __restrict__ Kg,
    float* __restrict__ uv_out,
    float* __restrict__ d_out)
{
    const int b = blockIdx.y;
    const int strip = blockIdx.x;

    // First pixel this thread touches (within the image)
    const int t4 = threadIdx.x * 4;
    const int p_img0 = strip * STRIP_PIX + t4;

    const float* dptr = depth + (size_t)b * NPIX + p_img0;

    // Issue the first depth load BEFORE the constant prologue: independent of
    // the constants, its DRAM latency hides the warp-0 shuffle pipeline.
    float4 cur = *reinterpret_cast<const float4*>(dptr);

    __shared__ float s[12];

    // ---- lane-parallel per-batch constant computation (warp 0 only) ----
    if (threadIdx.x < 32) {
        const int i = threadIdx.x;
        const int c = (i / 3) % 3;
        const int d = i % 3;
        const unsigned FM = 0xFFFFFFFFu;

        float r0v = 0.f, r1v = 0.f, kv = 0.f, t0v = 0.f, t1v = 0.f;
        if (i < 9) {
            r0v = R0g[b * 9 + i];
            r1v = R1g[b * 9 + i];
            kv  = Kg[i];
        }
        if (i < 3) {
            t0v = t0g[b * 3 + i];
            t1v = t1g[b * 3 + i];
        }

        // M(c,d) = sum_e R0[c,e] * R1[d,e]   (R0 @ R1^T)
        float Mv = 0.f;
        #pragma unroll
        for (int e = 0; e < 3; e++)
            Mv = fmaf(__shfl_sync(FM, r0v, 3 * c + e),
                      __shfl_sync(FM, r1v, 3 * d + e), Mv);

        // A(c,d) = sum_e M[c,e] * K[d,e]     (M @ K^T)
        float Av = 0.f;
        #pragma unroll
        for (int e = 0; e < 3; e++)
            Av = fmaf(__shfl_sync(FM, Mv, 3 * c + e),
                      __shfl_sync(FM, kv, 3 * d + e), Av);

        // cofactor of K at (c,d) via cyclic indexing (sign-correct)
        const int rr1 = (c + 1) % 3, rr2 = (c + 2) % 3;
        const int cc1 = (d + 1) % 3, cc2 = (d + 2) % 3;
        const float cofv =
            __shfl_sync(FM, kv, 3 * rr1 + cc1) * __shfl_sync(FM, kv, 3 * rr2 + cc2)
          - __shfl_sync(FM, kv, 3 * rr1 + cc2) * __shfl_sync(FM, kv, 3 * rr2 + cc1);

        // det = sum_e K[0,e] * cof(0,e)
        float det = 0.f;
        #pragma unroll
        for (int e = 0; e < 3; e++)
            det = fmaf(__shfl_sync(FM, kv, e), __shfl_sync(FM, cofv, e), det);
        const float rdet = 1.0f / det;

        // Ki(c,d) = cof(d,c) / det   (adjugate transpose)
        const float Kiv = __shfl_sync(FM, cofv, 3 * d + c) * rdet;

        // B(c,d) = sum_k Ki[k,c] * A[k,d]    (Ki^T @ A)
        float Bv = 0.f;
        #pragma unroll
        for (int k = 0; k < 3; k++)
            Bv = fmaf(__shfl_sync(FM, Kiv, 3 * k + c),
                      __shfl_sync(FM, Av, 3 * k + d), Bv);

        // bias(d') for lanes 0..2: t1 @ K^T - t0 @ A
        float biasv = 0.f;
        #pragma unroll
        for (int e = 0; e < 3; e++) {
            biasv = fmaf(__shfl_sync(FM, t1v, e),
                         __shfl_sync(FM, kv, 3 * d + e), biasv);
            biasv = fmaf(-__shfl_sync(FM, t0v, e),
                         __shfl_sync(FM, Av, 3 * e + d), biasv);
        }

        if (i < 9) s[i] = Bv;
        if (i < 3) s[9 + i] = biasv;
    }
    __syncthreads();

    const float B00 = s[0], B01 = s[1], B02 = s[2];   // per-col increments
    const float B10 = s[3], B11 = s[4], B12 = s[5];   // per-row coeffs
    const float B20 = s[6], B21 = s[7], B22 = s[8];   // constant
    const float b0 = s[9], b1 = s[10], b2 = s[11];

    // col is fixed per thread across iterations; row advances by exactly 2
    // per iteration (ITER_PIX = 1024 = 2 rows of 512).
    const float col = (float)(t4 & 511);
    const float row0 = (float)(p_img0 >> 9);

    float br0 = fmaf(col, B00, fmaf(row0, B10, B20));
    float br1 = fmaf(col, B01, fmaf(row0, B11, B21));
    float br2 = fmaf(col, B02, fmaf(row0, B12, B22));
    const float dR0 = 2.0f * B10, dR1 = 2.0f * B11, dR2 = 2.0f * B12;

    float* uvp = uv_out + ((size_t)b * NPIX + p_img0) * 2;
    float* ddp = d_out + (size_t)b * NPIX + p_img0;

    #pragma unroll 2
    for (int it = 0; it < ITERS; it++) {
        // Prefetch next iteration's depth before any compute/stores.
        float4 nxt = cur;
        if (it + 1 < ITERS)
            nxt = *reinterpret_cast<const float4*>(dptr + (it + 1) * ITER_PIX);

        const float dv[4] = {cur.x, cur.y, cur.z, cur.w};
        float rr0 = br0, rr1 = br1, rr2 = br2;

        float u[4], v[4], dd[4];
        #pragma unroll
        for (int i = 0; i < 4; i++) {
            const float u3 = fmaf(dv[i], rr0, b0);
            const float v3 = fmaf(dv[i], rr1, b1);
            const float w3 = fmaf(dv[i], rr2, b2);
            dd[i] = w3;
            const float rcp = __frcp_rn(fmaxf(w3, 0.0f) + 1e-12f);
            u[i] = u3 * rcp;
            v[i] = v3 * rcp;
            rr0 += B00; rr1 += B01; rr2 += B02;  // advance one column
        }

        float4 uvA, uvB, dq;
        uvA.x = u[0]; uvA.y = v[0]; uvA.z = u[1]; uvA.w = v[1];
        uvB.x = u[2]; uvB.y = v[2]; uvB.z = u[3]; uvB.w = v[3];
        dq.x = dd[0]; dq.y = dd[1]; dq.z = dd[2]; dq.w = dd[3];

        *reinterpret_cast<float4*>(uvp + (size_t)it * ITER_PIX * 2)     = uvA;
        *reinterpret_cast<float4*>(uvp + (size_t)it * ITER_PIX * 2 + 4) = uvB;
        *reinterpret_cast<float4*>(ddp + (size_t)it * ITER_PIX)         = dq;

        cur = nxt;
        br0 += dR0; br1 += dR1; br2 += dR2;  // advance two rows
    }
}

extern "C" void kernel_launch(void* const* d_in, const int* in_sizes, int n_in,
                              void* d_out, int out_size)
{
    // metadata order: depth0, R0, t0, R1, t1, K, ray
    const float* depth = (const float*)d_in[0];
    const float* R0    = (const float*)d_in[1];
    const float* t0    = (const float*)d_in[2];
    const float* R1    = (const float*)d_in[3];
    const float* t1    = (const float*)d_in[4];
    const float* K     = (const float*)d_in[5];

    float* uv_out = (float*)d_out;                           // BS*N*2 floats
    float* dd_out = (float*)d_out + (size_t)BSZ * NPIX * 2;  // BS*N floats

    dim3 grid(STRIPS, BSZ);   // 1024 blocks ~= one resident wave on 148 SMs
    uv_transform_kernel<<<grid, THREADS>>>(depth, R0, t0, R1, t1, K, uv_out, dd_out);
}

// round 9
// speedup vs baseline: 1.3712x; 1.3712x over previous
#include <cuda_runtime.h>

#define HH 512
#define WW 512
#define NPIX (HH*WW)
#define BSZ 64
#define PIX_PER_THREAD 4
#define THREADS 256

__global__ __launch_bounds__(THREADS, 7) void uv_transform_kernel(
    const float* __restrict__ depth,
    const float* __restrict__ R0g,
    const float* __restrict__ t0g,
    const float* __restrict__ R1g,
    const float* __restrict__ t1g,
    const float* __restrict__ Kg,
    float* __restrict__ uv_out,
    float* __restrict__ d_out)
{
    const int b = blockIdx.y;
    const int p0 = (blockIdx.x * THREADS + threadIdx.x) * PIX_PER_THREAD;

    // Issue the depth load FIRST: independent of the per-batch constants, so
    // its ~600-cycle DRAM latency hides this warp's shuffle pipeline below.
    const float4 dep = *reinterpret_cast<const float4*>(depth + (size_t)b * NPIX + p0);

    // ---- warp-local per-batch constant computation (every warp, no barrier) ----
    // Lane i (i<9) owns matrix entry (c,d) = (i/3, i%3). All 3x3 algebra is
    // done with warp shuffles; results broadcast to all lanes at the end.
    const int lane = threadIdx.x & 31;
    const int c = (lane / 3) % 3;
    const int d = lane % 3;
    const unsigned FM = 0xFFFFFFFFu;

    float r0v = 0.f, r1v = 0.f, kv = 0.f, t0v = 0.f, t1v = 0.f;
    if (lane < 9) {
        r0v = R0g[b * 9 + lane];
        r1v = R1g[b * 9 + lane];
        kv  = Kg[lane];
    }
    if (lane < 3) {
        t0v = t0g[b * 3 + lane];
        t1v = t1g[b * 3 + lane];
    }

    // M(c,d) = sum_e R0[c,e] * R1[d,e]   (R0 @ R1^T)
    float Mv = 0.f;
    #pragma unroll
    for (int e = 0; e < 3; e++)
        Mv = fmaf(__shfl_sync(FM, r0v, 3 * c + e),
                  __shfl_sync(FM, r1v, 3 * d + e), Mv);

    // A(c,d) = sum_e M[c,e] * K[d,e]     (M @ K^T)
    float Av = 0.f;
    #pragma unroll
    for (int e = 0; e < 3; e++)
        Av = fmaf(__shfl_sync(FM, Mv, 3 * c + e),
                  __shfl_sync(FM, kv, 3 * d + e), Av);

    // cofactor of K at (c,d) via cyclic indexing (sign-correct)
    {
        // nothing here needs lanes >= 9 to be correct; they compute garbage
    }
    const int rr1 = (c + 1) % 3, rr2 = (c + 2) % 3;
    const int cc1 = (d + 1) % 3, cc2 = (d + 2) % 3;
    const float cofv =
        __shfl_sync(FM, kv, 3 * rr1 + cc1) * __shfl_sync(FM, kv, 3 * rr2 + cc2)
      - __shfl_sync(FM, kv, 3 * rr1 + cc2) * __shfl_sync(FM, kv, 3 * rr2 + cc1);

    // det = sum_e K[0,e] * cof(0,e)
    float det = 0.f;
    #pragma unroll
    for (int e = 0; e < 3; e++)
        det = fmaf(__shfl_sync(FM, kv, e), __shfl_sync(FM, cofv, e), det);
    const float rdet = 1.0f / det;

    // Ki(c,d) = cof(d,c) / det   (adjugate transpose)
    const float Kiv = __shfl_sync(FM, cofv, 3 * d + c) * rdet;

    // Bv(c,d) = sum_k Ki[k,c] * A[k,d]   (Ki^T @ A)
    float Bv = 0.f;
    #pragma unroll
    for (int k = 0; k < 3; k++)
        Bv = fmaf(__shfl_sync(FM, Kiv, 3 * k + c),
                  __shfl_sync(FM, Av, 3 * k + d), Bv);

    // biasv for lanes 0..2 (d = lane): t1 @ K^T - t0 @ A
    float biasv = 0.f;
    #pragma unroll
    for (int e = 0; e < 3; e++) {
        biasv = fmaf(__shfl_sync(FM, t1v, e),
                     __shfl_sync(FM, kv, 3 * d + e), biasv);
        biasv = fmaf(-__shfl_sync(FM, t0v, e),
                     __shfl_sync(FM, Av, 3 * e + d), biasv);
    }

    // Broadcast the 12 constants to all lanes (no smem, no barrier).
    const float B00 = __shfl_sync(FM, Bv, 0);
    const float B01 = __shfl_sync(FM, Bv, 1);
    const float B02 = __shfl_sync(FM, Bv, 2);
    const float B10 = __shfl_sync(FM, Bv, 3);
    const float B11 = __shfl_sync(FM, Bv, 4);
    const float B12 = __shfl_sync(FM, Bv, 5);
    const float B20 = __shfl_sync(FM, Bv, 6);
    const float B21 = __shfl_sync(FM, Bv, 7);
    const float B22 = __shfl_sync(FM, Bv, 8);
    const float b0  = __shfl_sync(FM, biasv, 0);
    const float b1  = __shfl_sync(FM, biasv, 1);
    const float b2  = __shfl_sync(FM, biasv, 2);

    const float dv[4] = {dep.x, dep.y, dep.z, dep.w};

    // pixel coords: 4 consecutive pixels share a row (512 % 4 == 0)
    const float row = (float)(p0 >> 9);
    const float col = (float)(p0 & 511);

    float r0 = fmaf(col, B00, fmaf(row, B10, B20));
    float r1 = fmaf(col, B01, fmaf(row, B11, B21));
    float r2 = fmaf(col, B02, fmaf(row, B12, B22));

    float u[4], v[4], dd[4];
    #pragma unroll
    for (int i = 0; i < PIX_PER_THREAD; i++) {
        const float u3 = fmaf(dv[i], r0, b0);
        const float v3 = fmaf(dv[i], r1, b1);
        const float w3 = fmaf(dv[i], r2, b2);
        dd[i] = w3;
        const float rcp = __frcp_rn(fmaxf(w3, 0.0f) + 1e-12f);
        u[i] = u3 * rcp;
        v[i] = v3 * rcp;
        r0 += B00; r1 += B01; r2 += B02;  // advance one column
    }

    // uv: (BS, N, 2) interleaved -> 2x float4 per thread
    const size_t uvbase = ((size_t)b * NPIX + p0) * 2;
    float4 uvA, uvB;
    uvA.x = u[0]; uvA.y = v[0]; uvA.z = u[1]; uvA.w = v[1];
    uvB.x = u[2]; uvB.y = v[2]; uvB.z = u[3]; uvB.w = v[3];
    *reinterpret_cast<float4*>(uv_out + uvbase)     = uvA;
    *reinterpret_cast<float4*>(uv_out + uvbase + 4) = uvB;

    // d: (BS, N, 1) -> 1x float4
    float4 dq;
    dq.x = dd[0]; dq.y = dd[1]; dq.z = dd[2]; dq.w = dd[3];
    *reinterpret_cast<float4*>(d_out + (size_t)b * NPIX + p0) = dq;
}

extern "C" void kernel_launch(void* const* d_in, const int* in_sizes, int n_in,
                              void* d_out, int out_size)
{
    // metadata order: depth0, R0, t0, R1, t1, K, ray
    const float* depth = (const float*)d_in[0];
    const float* R0    = (const float*)d_in[1];
    const float* t0    = (const float*)d_in[2];
    const float* R1    = (const float*)d_in[3];
    const float* t1    = (const float*)d_in[4];
    const float* K     = (const float*)d_in[5];

    float* uv_out = (float*)d_out;                           // BS*N*2 floats
    float* dd_out = (float*)d_out + (size_t)BSZ * NPIX * 2;  // BS*N floats

    dim3 grid(NPIX / (THREADS * PIX_PER_THREAD), BSZ);
    uv_transform_kernel<<<grid, THREADS>>>(depth, R0, t0, R1, t1, K, uv_out, dd_out);
}